// round 1
// baseline (speedup 1.0000x reference)
#include <cuda_runtime.h>
#include <math.h>

#define BB   8
#define NN   2048
#define KK   16
#define CIN  128
#define HID  128
#define COUT 128
#define MSGD 259
#define MROW 260   // padded row stride for msg (divisible by 4)

// Flag: is idx stored as int64 (1) or int32 (0)?
__device__ int g_idx_is64;

__global__ void detect_idx_kernel(const int* __restrict__ idx_raw) {
    if (threadIdx.x == 0) {
        int is64 = 1;
        #pragma unroll 1
        for (int i = 0; i < 64; ++i) {
            if (idx_raw[2 * i + 1] != 0) { is64 = 0; break; }
        }
        g_idx_is64 = is64;
    }
}

__device__ __forceinline__ float gelu_exact(float x) {
    // exact gelu: x * 0.5 * (1 + erf(x / sqrt(2)))
    return 0.5f * x * (1.0f + erff(x * 0.70710678118654752440f));
}

__global__ __launch_bounds__(128) void edgeconv_kernel(
    const float* __restrict__ h,     // (B,N,CIN)
    const float* __restrict__ pos,   // (B,N,3)
    const int*   __restrict__ idx_raw,
    const float* __restrict__ W1,    // (MSGD,HID) row-major
    const float* __restrict__ b1,    // (HID)
    const float* __restrict__ W2,    // (HID,COUT)
    const float* __restrict__ b2,    // (COUT)
    const float* __restrict__ gamma, // (COUT)
    const float* __restrict__ beta,  // (COUT)
    float*       __restrict__ out)   // (B,N,COUT)
{
    __shared__ float msg_s[KK * MROW];   // 16 x 260  (16.25 KB)
    __shared__ float x1_s[KK * HID];     // 16 x 128  (8 KB)
    __shared__ int   jidx[KK];
    __shared__ float red_s[4];

    const int t    = threadIdx.x;
    const int node = blockIdx.x;
    const int b    = node / NN;
    const int n    = node - b * NN;

    const float* hb = h   + (size_t)b * NN * CIN;
    const float* pb = pos + (size_t)b * NN * 3;

    // ---- load neighbor indices ----
    if (t < KK) {
        const int is64 = g_idx_is64;
        long e = (long)node * KK + t;
        jidx[t] = is64 ? idx_raw[2 * e] : idx_raw[e];
    }
    __syncthreads();

    // ---- build msg = [h_i, h_j - h_i, rel] in smem ----
    const float hi = hb[n * CIN + t];
    #pragma unroll 1
    for (int k = 0; k < KK; ++k) {
        const int j = jidx[k];
        const float hj = hb[j * CIN + t];
        msg_s[k * MROW + t]       = hi;
        msg_s[k * MROW + CIN + t] = hj - hi;
        if (t < 3) {
            msg_s[k * MROW + 2 * CIN + t] = pb[j * 3 + t] - pb[n * 3 + t];
        }
    }
    __syncthreads();

    // ---- GEMM1: x1[k][t] = gelu(sum_d msg[k][d] * W1[d][t] + b1[t]) ----
    float acc[KK];
    {
        const float bv = b1[t];
        #pragma unroll
        for (int k = 0; k < KK; ++k) acc[k] = bv;

        const float* w1c = W1 + t;   // column t, stride HID
        #pragma unroll 2
        for (int dd = 0; dd < 64; ++dd) {     // d = 4*dd .. 4*dd+3, covers 0..255
            const int d0 = 4 * dd;
            const float w0 = w1c[(d0 + 0) * HID];
            const float w1v = w1c[(d0 + 1) * HID];
            const float w2v = w1c[(d0 + 2) * HID];
            const float w3v = w1c[(d0 + 3) * HID];
            #pragma unroll
            for (int k = 0; k < KK; ++k) {
                const float4 m = *reinterpret_cast<const float4*>(&msg_s[k * MROW + d0]);
                acc[k] = fmaf(m.x, w0,  acc[k]);
                acc[k] = fmaf(m.y, w1v, acc[k]);
                acc[k] = fmaf(m.z, w2v, acc[k]);
                acc[k] = fmaf(m.w, w3v, acc[k]);
            }
        }
        // remainder d = 256..258 (the 3 rel dims)
        #pragma unroll
        for (int d = 256; d < MSGD; ++d) {
            const float w = w1c[d * HID];
            #pragma unroll
            for (int k = 0; k < KK; ++k)
                acc[k] = fmaf(msg_s[k * MROW + d], w, acc[k]);
        }
    }
    #pragma unroll
    for (int k = 0; k < KK; ++k)
        x1_s[k * HID + t] = gelu_exact(acc[k]);
    __syncthreads();

    // ---- GEMM2: x2[k][t] = gelu(sum_d x1[k][d] * W2[d][t] + b2[t]) ----
    float acc2[KK];
    {
        const float bv = b2[t];
        #pragma unroll
        for (int k = 0; k < KK; ++k) acc2[k] = bv;

        const float* w2c = W2 + t;
        #pragma unroll 2
        for (int dd = 0; dd < 32; ++dd) {     // d = 4*dd .. 4*dd+3, covers 0..127
            const int d0 = 4 * dd;
            const float w0 = w2c[(d0 + 0) * HID];
            const float w1v = w2c[(d0 + 1) * HID];
            const float w2v = w2c[(d0 + 2) * HID];
            const float w3v = w2c[(d0 + 3) * HID];
            #pragma unroll
            for (int k = 0; k < KK; ++k) {
                const float4 m = *reinterpret_cast<const float4*>(&x1_s[k * HID + d0]);
                acc2[k] = fmaf(m.x, w0,  acc2[k]);
                acc2[k] = fmaf(m.y, w1v, acc2[k]);
                acc2[k] = fmaf(m.z, w2v, acc2[k]);
                acc2[k] = fmaf(m.w, w3v, acc2[k]);
            }
        }
    }

    // ---- gelu + max over k ----
    float v = -INFINITY;
    #pragma unroll
    for (int k = 0; k < KK; ++k)
        v = fmaxf(v, gelu_exact(acc2[k]));

    // ---- LayerNorm over 128 channels ----
    // mean
    float s = v;
    #pragma unroll
    for (int o = 16; o > 0; o >>= 1) s += __shfl_xor_sync(0xffffffffu, s, o);
    if ((t & 31) == 0) red_s[t >> 5] = s;
    __syncthreads();
    const float mean = (red_s[0] + red_s[1] + red_s[2] + red_s[3]) * (1.0f / COUT);
    __syncthreads();   // everyone done reading red_s before reuse

    const float dv = v - mean;
    float q = dv * dv;
    #pragma unroll
    for (int o = 16; o > 0; o >>= 1) q += __shfl_xor_sync(0xffffffffu, q, o);
    if ((t & 31) == 0) red_s[t >> 5] = q;
    __syncthreads();
    const float var = (red_s[0] + red_s[1] + red_s[2] + red_s[3]) * (1.0f / COUT);

    out[(size_t)node * COUT + t] = dv * rsqrtf(var + 1e-5f) * gamma[t] + beta[t];
}

extern "C" void kernel_launch(void* const* d_in, const int* in_sizes, int n_in,
                              void* d_out, int out_size) {
    const float* h     = (const float*)d_in[0];
    const float* pos   = (const float*)d_in[1];
    const int*   idx   = (const int*)  d_in[2];  // int32 or int64 words, detected at runtime
    const float* W1    = (const float*)d_in[3];
    const float* b1    = (const float*)d_in[4];
    const float* W2    = (const float*)d_in[5];
    const float* b2    = (const float*)d_in[6];
    const float* gamma = (const float*)d_in[7];
    const float* beta  = (const float*)d_in[8];
    float*       out   = (float*)d_out;

    detect_idx_kernel<<<1, 32>>>(idx);
    edgeconv_kernel<<<BB * NN, 128>>>(h, pos, idx, W1, b1, W2, b2, gamma, beta, out);
}

// round 2
// speedup vs baseline: 3.2472x; 3.2472x over previous
#include <cuda_runtime.h>
#include <math.h>

#define BB   8
#define NN   2048
#define KK   16
#define CIN  128
#define HID  128
#define COUT 128
#define NNODE (BB * NN)
#define PN   8     // nodes per block in precompute

// scratch: per-node projections  A = h@(W1a-W1b)+b1,  U = h@W1b
__device__ float g_A[NNODE * HID];
__device__ float g_U[NNODE * HID];
__device__ int   g_idx_is64;

__global__ void detect_idx_kernel(const int* __restrict__ idx_raw) {
    if (threadIdx.x == 0) {
        int is64 = 1;
        #pragma unroll 1
        for (int i = 0; i < 64; ++i) {
            if (idx_raw[2 * i + 1] != 0) { is64 = 0; break; }
        }
        g_idx_is64 = is64;
    }
}

__device__ __forceinline__ float gelu_exact(float x) {
    return 0.5f * x * (1.0f + erff(x * 0.70710678118654752440f));
}

// ---------------------------------------------------------------------------
// Precompute: for every node n, A[n][t] = sum_d h[n][d]*(W1[d][t]-W1[128+d][t]) + b1[t]
//                               U[n][t] = sum_d h[n][d]* W1[128+d][t]
// 8 nodes per block; weights amortized across the 8 nodes.
// ---------------------------------------------------------------------------
__global__ __launch_bounds__(128) void precompute_kernel(
    const float* __restrict__ h,   // (NNODE, CIN)
    const float* __restrict__ W1,  // (259, HID)
    const float* __restrict__ b1)  // (HID)
{
    __shared__ float hs[PN][CIN];
    const int t     = threadIdx.x;
    const int node0 = blockIdx.x * PN;

    #pragma unroll
    for (int i = 0; i < PN; ++i)
        hs[i][t] = h[(size_t)(node0 + i) * CIN + t];
    __syncthreads();

    float accA[PN], accU[PN];
    const float bv = b1[t];
    #pragma unroll
    for (int i = 0; i < PN; ++i) { accA[i] = bv; accU[i] = 0.0f; }

    #pragma unroll 2
    for (int dd = 0; dd < CIN / 4; ++dd) {
        const int d0 = 4 * dd;
        float wa[4], wb[4];
        #pragma unroll
        for (int j = 0; j < 4; ++j) {
            const float w1a = W1[(d0 + j) * HID + t];
            const float w1b = W1[(CIN + d0 + j) * HID + t];
            wb[j] = w1b;
            wa[j] = w1a - w1b;
        }
        #pragma unroll
        for (int i = 0; i < PN; ++i) {
            const float4 m = *reinterpret_cast<const float4*>(&hs[i][d0]);
            accA[i] = fmaf(m.x, wa[0], accA[i]);
            accA[i] = fmaf(m.y, wa[1], accA[i]);
            accA[i] = fmaf(m.z, wa[2], accA[i]);
            accA[i] = fmaf(m.w, wa[3], accA[i]);
            accU[i] = fmaf(m.x, wb[0], accU[i]);
            accU[i] = fmaf(m.y, wb[1], accU[i]);
            accU[i] = fmaf(m.z, wb[2], accU[i]);
            accU[i] = fmaf(m.w, wb[3], accU[i]);
        }
    }
    #pragma unroll
    for (int i = 0; i < PN; ++i) {
        g_A[(size_t)(node0 + i) * HID + t] = accA[i];
        g_U[(size_t)(node0 + i) * HID + t] = accU[i];
    }
}

// ---------------------------------------------------------------------------
// Main: per node — x1[k] = gelu(A[n] + U[j_k] + rel_k @ W1c); GEMM2 + gelu;
// max over k; LayerNorm.
// ---------------------------------------------------------------------------
__global__ __launch_bounds__(128) void edgeconv_kernel(
    const float* __restrict__ pos,     // (B,N,3)
    const int*   __restrict__ idx_raw,
    const float* __restrict__ W1,      // rows 256..258 used (rel weights)
    const float* __restrict__ W2,      // (HID, COUT)
    const float* __restrict__ b2,
    const float* __restrict__ gamma,
    const float* __restrict__ beta,
    float*       __restrict__ out)     // (B,N,COUT)
{
    __shared__ int   jidx[KK];
    __shared__ float rel_s[KK][4];
    __shared__ float x1_s[KK][HID];
    __shared__ float pmax[2][COUT];
    __shared__ float red_s[4];

    const int t    = threadIdx.x;
    const int node = blockIdx.x;
    const int b    = node >> 11;          // node / NN
    const int n    = node & (NN - 1);
    const float* pb = pos + (size_t)b * NN * 3;

    if (t < KK) {
        const int is64 = g_idx_is64;
        long e = (long)node * KK + t;
        jidx[t] = is64 ? idx_raw[2 * e] : idx_raw[e];
    }
    __syncthreads();

    // relative positions (48 threads, tiny)
    if (t < 3 * KK) {
        const int k = t / 3, c = t - 3 * k;
        rel_s[k][c] = pb[jidx[k] * 3 + c] - pb[n * 3 + c];
    }

    // per-thread: A[n][t], the 3 rel-weight entries, and gathered U rows
    const float a  = g_A[(size_t)node * HID + t];
    const float wc0 = W1[(2 * CIN + 0) * HID + t];
    const float wc1 = W1[(2 * CIN + 1) * HID + t];
    const float wc2 = W1[(2 * CIN + 2) * HID + t];
    float uk[KK];
    #pragma unroll
    for (int k = 0; k < KK; ++k)
        uk[k] = g_U[((size_t)b * NN + jidx[k]) * HID + t];
    __syncthreads();

    #pragma unroll
    for (int k = 0; k < KK; ++k) {
        float v = a + uk[k];
        v = fmaf(rel_s[k][0], wc0, v);
        v = fmaf(rel_s[k][1], wc1, v);
        v = fmaf(rel_s[k][2], wc2, v);
        x1_s[k][t] = gelu_exact(v);
    }
    __syncthreads();

    // ---- GEMM2, 2 cols x 8 k per thread ----
    const int half  = t >> 6;       // 0: k=0..7, 1: k=8..15
    const int u     = t & 63;
    const int c0    = 2 * u;
    const int kbase = half * 8;

    float acc0[8], acc1[8];
    {
        const float2 bv2 = *reinterpret_cast<const float2*>(&b2[c0]);
        #pragma unroll
        for (int i = 0; i < 8; ++i) { acc0[i] = bv2.x; acc1[i] = bv2.y; }
    }

    #pragma unroll 2
    for (int dd = 0; dd < HID / 4; ++dd) {
        const int d0 = 4 * dd;
        float2 w[4];
        #pragma unroll
        for (int j = 0; j < 4; ++j)
            w[j] = *reinterpret_cast<const float2*>(&W2[(d0 + j) * COUT + c0]);
        #pragma unroll
        for (int kk = 0; kk < 8; ++kk) {
            const float4 m = *reinterpret_cast<const float4*>(&x1_s[kbase + kk][d0]);
            acc0[kk] = fmaf(m.x, w[0].x, acc0[kk]);
            acc1[kk] = fmaf(m.x, w[0].y, acc1[kk]);
            acc0[kk] = fmaf(m.y, w[1].x, acc0[kk]);
            acc1[kk] = fmaf(m.y, w[1].y, acc1[kk]);
            acc0[kk] = fmaf(m.z, w[2].x, acc0[kk]);
            acc1[kk] = fmaf(m.z, w[2].y, acc1[kk]);
            acc0[kk] = fmaf(m.w, w[3].x, acc0[kk]);
            acc1[kk] = fmaf(m.w, w[3].y, acc1[kk]);
        }
    }

    // gelu + partial max over this thread's 8 k
    float v0 = -INFINITY, v1 = -INFINITY;
    #pragma unroll
    for (int kk = 0; kk < 8; ++kk) {
        v0 = fmaxf(v0, gelu_exact(acc0[kk]));
        v1 = fmaxf(v1, gelu_exact(acc1[kk]));
    }
    *reinterpret_cast<float2*>(&pmax[half][c0]) = make_float2(v0, v1);
    __syncthreads();

    // merge halves: thread t owns channel t again
    const float v = fmaxf(pmax[0][t], pmax[1][t]);

    // ---- LayerNorm over 128 channels ----
    float s = v;
    #pragma unroll
    for (int o = 16; o > 0; o >>= 1) s += __shfl_xor_sync(0xffffffffu, s, o);
    if ((t & 31) == 0) red_s[t >> 5] = s;
    __syncthreads();
    const float mean = (red_s[0] + red_s[1] + red_s[2] + red_s[3]) * (1.0f / COUT);
    __syncthreads();

    const float dv = v - mean;
    float q = dv * dv;
    #pragma unroll
    for (int o = 16; o > 0; o >>= 1) q += __shfl_xor_sync(0xffffffffu, q, o);
    if ((t & 31) == 0) red_s[t >> 5] = q;
    __syncthreads();
    const float var = (red_s[0] + red_s[1] + red_s[2] + red_s[3]) * (1.0f / COUT);

    out[(size_t)node * COUT + t] = dv * rsqrtf(var + 1e-5f) * gamma[t] + beta[t];
}

extern "C" void kernel_launch(void* const* d_in, const int* in_sizes, int n_in,
                              void* d_out, int out_size) {
    const float* h     = (const float*)d_in[0];
    const float* pos   = (const float*)d_in[1];
    const int*   idx   = (const int*)  d_in[2];
    const float* W1    = (const float*)d_in[3];
    const float* b1    = (const float*)d_in[4];
    const float* W2    = (const float*)d_in[5];
    const float* b2    = (const float*)d_in[6];
    const float* gamma = (const float*)d_in[7];
    const float* beta  = (const float*)d_in[8];
    float*       out   = (float*)d_out;

    detect_idx_kernel<<<1, 32>>>(idx);
    precompute_kernel<<<NNODE / PN, 128>>>(h, W1, b1);
    edgeconv_kernel<<<NNODE, 128>>>(pos, idx, W1, W2, b2, gamma, beta, out);
}